// round 6
// baseline (speedup 1.0000x reference)
#include <cuda_runtime.h>

#define JAX_PARTITIONABLE 1

// ---------------- scratch (__device__ globals; no allocation) ----------------
__device__ float g_T[8192 * 128];          // X_in @ theta
__device__ float g_U[8192 * 128];          // xi @ w_trans
__device__ float g_X[8192 * 128];          // X1 then X2
__device__ float g_msg[4096 * 128];        // edge messages (ew-scaled)
__device__ float g_msgP[8 * 4096 * 128];   // split-K partials for Hs GEMM
__device__ float g_ZP[4 * 8192 * 128];     // split-K partials for Ht^T GEMM

// ------------------------------- helpers ------------------------------------
__device__ __forceinline__ unsigned f2tf32(float f) {
    unsigned u;
    asm("cvt.rna.tf32.f32 %0, %1;" : "=r"(u) : "f"(f));
    return u;
}
// split f into tf32 hi + tf32 lo (3xTF32 scheme)
__device__ __forceinline__ void split1(float f, unsigned& hi, unsigned& lo) {
    hi = f2tf32(f);
    lo = f2tf32(f - __uint_as_float(hi));
}
__device__ __forceinline__ void split4(float4 f, uint4& hi, uint4& lo) {
    split1(f.x, hi.x, lo.x);
    split1(f.y, hi.y, lo.y);
    split1(f.z, hi.z, lo.z);
    split1(f.w, hi.w, lo.w);
}
__device__ __forceinline__ void mma8(float c[4], const unsigned a[4], const unsigned b[2]) {
    asm volatile(
        "mma.sync.aligned.m16n8k8.row.col.f32.tf32.tf32.f32 "
        "{%0,%1,%2,%3},{%4,%5,%6,%7},{%8,%9},{%0,%1,%2,%3};"
        : "+f"(c[0]), "+f"(c[1]), "+f"(c[2]), "+f"(c[3])
        : "r"(a[0]), "r"(a[1]), "r"(a[2]), "r"(a[3]), "r"(b[0]), "r"(b[1]));
}
__device__ __forceinline__ unsigned rotl32(unsigned v, int s) {
    return __funnelshift_l(v, v, s);
}

// JAX threefry2x32, key = (0, 42). Random bits for flat element j of (8192,128).
__device__ __forceinline__ unsigned jax_dropout_bits(unsigned j) {
    const unsigned k0 = 0u, k1 = 42u;
    const unsigned ks2 = k0 ^ k1 ^ 0x1BD11BDAu;
    unsigned x0, x1;
#if JAX_PARTITIONABLE
    x0 = 0u + k0;               // hi32 of 64-bit iota
    x1 = j + k1;                // lo32
#else
    const unsigned HALF = 524288u;
    unsigned i = (j < HALF) ? j : (j - HALF);
    x0 = i + k0;
    x1 = (i + HALF) + k1;
#endif
#define TFR(r) do { x0 += x1; x1 = rotl32(x1, (r)); x1 ^= x0; } while (0)
    TFR(13); TFR(15); TFR(26); TFR(6);   x0 += k1;  x1 += ks2 + 1u;
    TFR(17); TFR(29); TFR(16); TFR(24);  x0 += ks2; x1 += k0 + 2u;
    TFR(13); TFR(15); TFR(26); TFR(6);   x0 += k0;  x1 += k1 + 3u;
    TFR(17); TFR(29); TFR(16); TFR(24);  x0 += k1;  x1 += ks2 + 4u;
    TFR(13); TFR(15); TFR(26); TFR(6);   x0 += ks2; x1 += k0 + 5u;
#undef TFR
#if JAX_PARTITIONABLE
    return x0 ^ x1;
#else
    return (j < 524288u) ? x0 : x1;
#endif
}

// ---------------------------- 3xTF32 GEMM ------------------------------------
// C[M,128] = op(A) @ B;  B is [K,128] row-major fp32.
//   TRANS_A=false: A is [M,K] row-major (row stride lda)
//   TRANS_A=true : A is [K,M] row-major (row stride lda), used as A^T
// Grid (M/128, S). Split s handles k in [s*k_iters*16, ...), writes a partial
// [M,128] image at Cp + s * gridDim.x * 128*128. With S=1, Cp is the result.
// 256 threads = 8 warps (4Mx2N), warp tile 32x64, m16n8k8 tf32.
// Each operand split hi/lo; products hi*hi + lo*hi + hi*lo (3xTF32),
// giving ~fp32-quality results (residual ~2^-22).
// Single-buffered smem (hi+lo tiles), next global tile prefetched to regs.
template <bool TRANS_A>
__global__ __launch_bounds__(256, 2)
void gemm_3xtf32(const float* __restrict__ A, const float* __restrict__ B,
                 float* __restrict__ Cp, int lda, int k_iters)
{
    const int ASZ = TRANS_A ? (16 * 136) : (128 * 20);
    __shared__ __align__(16) unsigned AsH[TRANS_A ? (16 * 136) : (128 * 20)];
    __shared__ __align__(16) unsigned AsL[TRANS_A ? (16 * 136) : (128 * 20)];
    __shared__ __align__(16) unsigned BsH[16 * 136];
    __shared__ __align__(16) unsigned BsL[16 * 136];
    (void)ASZ;

    const int m0 = blockIdx.x * 128;
    const int kbase = blockIdx.y * k_iters * 16;
    const int tid = threadIdx.x;
    const int lane = tid & 31;
    const int wid = tid >> 5;
    const int wm = (wid & 3) * 32;
    const int wn = (wid >> 2) * 64;
    const int g = lane >> 2;   // 0..7
    const int t = lane & 3;    // 0..3

    const float *aP0, *aP1;
    unsigned sA0, sA1;
    if (TRANS_A) {
        int r0 = tid >> 5, c = (tid & 31) * 4;       // k-rows, m-cols
        aP0 = A + (size_t)(kbase + r0) * lda + m0 + c;
        aP1 = A + (size_t)(kbase + r0 + 8) * lda + m0 + c;
        sA0 = r0 * 136 + c;  sA1 = (r0 + 8) * 136 + c;
    } else {
        int r0 = tid >> 2, c = (tid & 3) * 4;        // m-rows, k-cols
        aP0 = A + (size_t)(m0 + r0) * lda + kbase + c;
        aP1 = A + (size_t)(m0 + r0 + 64) * lda + kbase + c;
        sA0 = r0 * 20 + c;   sA1 = (r0 + 64) * 20 + c;
    }
    const int br = tid >> 5, bc = (tid & 31) * 4;
    const float* bP0 = B + (size_t)(kbase + br) * 128 + bc;
    const float* bP1 = B + (size_t)(kbase + br + 8) * 128 + bc;
    const unsigned sB0 = br * 136 + bc;
    const unsigned sB1 = (br + 8) * 136 + bc;

    float acc[2][8][4];
#pragma unroll
    for (int mt = 0; mt < 2; ++mt)
#pragma unroll
        for (int nt = 0; nt < 8; ++nt)
#pragma unroll
            for (int i = 0; i < 4; ++i) acc[mt][nt][i] = 0.f;

    // prefetch tile 0
    float4 fa0 = *(const float4*)aP0;
    float4 fa1 = *(const float4*)aP1;
    float4 fb0 = *(const float4*)bP0;
    float4 fb1 = *(const float4*)bP1;

    const size_t aStep = TRANS_A ? (size_t)16 * lda : (size_t)16;

    for (int it = 0; it < k_iters; ++it) {
        // stage current tile (split hi/lo)
        {
            uint4 h, l;
            split4(fa0, h, l); *(uint4*)&AsH[sA0] = h; *(uint4*)&AsL[sA0] = l;
            split4(fa1, h, l); *(uint4*)&AsH[sA1] = h; *(uint4*)&AsL[sA1] = l;
            split4(fb0, h, l); *(uint4*)&BsH[sB0] = h; *(uint4*)&BsL[sB0] = l;
            split4(fb1, h, l); *(uint4*)&BsH[sB1] = h; *(uint4*)&BsL[sB1] = l;
        }
        __syncthreads();

        // prefetch next tile (overlaps with mma work below)
        if (it + 1 < k_iters) {
            aP0 += aStep; aP1 += aStep; bP0 += 2048; bP1 += 2048;
            fa0 = *(const float4*)aP0;
            fa1 = *(const float4*)aP1;
            fb0 = *(const float4*)bP0;
            fb1 = *(const float4*)bP1;
        }

#pragma unroll
        for (int ks = 0; ks < 2; ++ks) {
            const int kk = ks * 8;
            unsigned aH[2][4], aL[2][4];
#pragma unroll
            for (int mt = 0; mt < 2; ++mt) {
                const int mb = wm + mt * 16;
                if (TRANS_A) {
                    const int i0 = (kk + t) * 136 + mb + g;
                    const int i1 = (kk + t + 4) * 136 + mb + g;
                    aH[mt][0] = AsH[i0];     aL[mt][0] = AsL[i0];
                    aH[mt][1] = AsH[i0 + 8]; aL[mt][1] = AsL[i0 + 8];
                    aH[mt][2] = AsH[i1];     aL[mt][2] = AsL[i1];
                    aH[mt][3] = AsH[i1 + 8]; aL[mt][3] = AsL[i1 + 8];
                } else {
                    const int i0 = (mb + g) * 20 + kk + t;
                    const int i1 = (mb + g + 8) * 20 + kk + t;
                    aH[mt][0] = AsH[i0];     aL[mt][0] = AsL[i0];
                    aH[mt][1] = AsH[i1];     aL[mt][1] = AsL[i1];
                    aH[mt][2] = AsH[i0 + 4]; aL[mt][2] = AsL[i0 + 4];
                    aH[mt][3] = AsH[i1 + 4]; aL[mt][3] = AsL[i1 + 4];
                }
            }
#pragma unroll
            for (int nt = 0; nt < 8; ++nt) {
                const int nb = wn + nt * 8;
                const int j0 = (kk + t) * 136 + nb + g;
                const int j1 = (kk + t + 4) * 136 + nb + g;
                unsigned bH[2] = { BsH[j0], BsH[j1] };
                unsigned bL[2] = { BsL[j0], BsL[j1] };
#pragma unroll
                for (int mt = 0; mt < 2; ++mt) {
                    mma8(acc[mt][nt], aH[mt], bH);   // hi*hi
                    mma8(acc[mt][nt], aL[mt], bH);   // lo*hi
                    mma8(acc[mt][nt], aH[mt], bL);   // hi*lo
                }
            }
        }
        __syncthreads();
    }

    float* Cb = Cp + (size_t)blockIdx.y * gridDim.x * (128 * 128) + (size_t)m0 * 128;
#pragma unroll
    for (int mt = 0; mt < 2; ++mt)
#pragma unroll
        for (int nt = 0; nt < 8; ++nt) {
            const int r = wm + mt * 16 + g;
            const int c = wn + nt * 8 + t * 2;
            *(float2*)&Cb[(size_t)r * 128 + c] = make_float2(acc[mt][nt][0], acc[mt][nt][1]);
            *(float2*)&Cb[(size_t)(r + 8) * 128 + c] = make_float2(acc[mt][nt][2], acc[mt][nt][3]);
        }
}

// ------------------------ reduce / epilogue kernels --------------------------
__global__ void reduce_msg_k(const float* __restrict__ P, const float* __restrict__ ew,
                             float* __restrict__ out)
{
    const int i = blockIdx.x * 256 + threadIdx.x;   // 4096*128 elems
    float s = 0.f;
#pragma unroll
    for (int j = 0; j < 8; ++j) s += P[(size_t)j * (4096 * 128) + i];
    out[i] = s * ew[i >> 7];
}

__global__ void reduce_x1_k(const float* __restrict__ P, const float* __restrict__ U,
                            const float* __restrict__ bias, float* __restrict__ X1)
{
    const int i = blockIdx.x * 256 + threadIdx.x;   // 8192*128 elems
    float s = U[i] + bias[i & 127];
#pragma unroll
    for (int j = 0; j < 4; ++j) s += P[(size_t)j * (8192 * 128) + i];
    s = (s >= 0.f) ? s : 0.01f * s;                      // leaky_relu
    const unsigned bits = jax_dropout_bits((unsigned)i);
    X1[i] = (bits & 0x80000000u) ? 0.f : (s + s);        // dropout p=0.5 -> x2 scale
}

__global__ void reduce_x2_k(const float* __restrict__ P, const float* __restrict__ U,
                            const float* __restrict__ bias, float* __restrict__ X2)
{
    const int i = blockIdx.x * 256 + threadIdx.x;
    float s = U[i] + bias[i & 127];
#pragma unroll
    for (int j = 0; j < 4; ++j) s += P[(size_t)j * (8192 * 128) + i];
    s = (s >= 0.f) ? s : 0.01f * s;                      // conv lrelu
    s = (s >= 0.f) ? s : 0.01f * s;                      // forward lrelu
    X2[i] = s;
}

__global__ void fc_k(const float* __restrict__ X, const float* __restrict__ state,
                     const float* __restrict__ fcw, const float* __restrict__ fcb,
                     float* __restrict__ out)
{
    const int n = blockIdx.x * 256 + threadIdx.x;   // 8192 rows
    const float4* xr = (const float4*)(X + (size_t)n * 128);
    const float4* w4 = (const float4*)fcw;
    float s = 0.f;
#pragma unroll
    for (int i = 0; i < 32; ++i) {
        float4 a = xr[i], b = w4[i];
        s += a.x * b.x + a.y * b.y + a.z * b.z + a.w * b.w;
    }
    out[n] = s + state[n] * fcw[128] + fcb[0];
}

// --------------------------------- launch ------------------------------------
extern "C" void kernel_launch(void* const* d_in, const int* in_sizes, int n_in,
                              void* d_out, int out_size)
{
    const float* xi   = (const float*)d_in[0];
    const float* x    = (const float*)d_in[1];
    const float* Ht   = (const float*)d_in[2];
    const float* Hs   = (const float*)d_in[3];
    const float* st   = (const float*)d_in[4];
    const float* w0   = (const float*)d_in[5];
    const float* th0  = (const float*)d_in[6];
    const float* ew0  = (const float*)d_in[7];
    const float* b0   = (const float*)d_in[8];
    const float* w1   = (const float*)d_in[9];
    const float* th1  = (const float*)d_in[10];
    const float* ew1  = (const float*)d_in[11];
    const float* b1   = (const float*)d_in[12];
    const float* fcw  = (const float*)d_in[13];
    const float* fcb  = (const float*)d_in[14];
    float* out = (float*)d_out;

    float *T, *U, *X, *M, *MP, *ZP;
    cudaGetSymbolAddress((void**)&T,  g_T);
    cudaGetSymbolAddress((void**)&U,  g_U);
    cudaGetSymbolAddress((void**)&X,  g_X);
    cudaGetSymbolAddress((void**)&M,  g_msg);
    cudaGetSymbolAddress((void**)&MP, g_msgP);
    cudaGetSymbolAddress((void**)&ZP, g_ZP);

    // ---- layer 0 ----
    gemm_3xtf32<false><<<dim3(64, 1), 256>>>(x,  th0, T,  128,  8);   // T = x @ theta0
    gemm_3xtf32<false><<<dim3(32, 8), 256>>>(Hs, T,   MP, 8192, 64);  // msg partials
    reduce_msg_k<<<2048, 256>>>(MP, ew0, M);
    gemm_3xtf32<false><<<dim3(64, 1), 256>>>(xi, w0,  U,  128,  8);   // U = xi @ W0
    gemm_3xtf32<true ><<<dim3(64, 4), 256>>>(Ht, M,   ZP, 8192, 64);  // Z partials
    reduce_x1_k<<<4096, 256>>>(ZP, U, b0, X);                         // X1

    // ---- layer 1 ----
    gemm_3xtf32<false><<<dim3(64, 1), 256>>>(X,  th1, T,  128,  8);
    gemm_3xtf32<false><<<dim3(32, 8), 256>>>(Hs, T,   MP, 8192, 64);
    reduce_msg_k<<<2048, 256>>>(MP, ew1, M);
    gemm_3xtf32<false><<<dim3(64, 1), 256>>>(xi, w1,  U,  128,  8);
    gemm_3xtf32<true ><<<dim3(64, 4), 256>>>(Ht, M,   ZP, 8192, 64);
    reduce_x2_k<<<4096, 256>>>(ZP, U, b1, X);                         // X2 (double lrelu)

    // ---- head ----
    fc_k<<<32, 256>>>(X, st, fcw, fcb, out);
}

// round 7
// speedup vs baseline: 1.0249x; 1.0249x over previous
#include <cuda_runtime.h>

#define JAX_PARTITIONABLE 1

// ---------------- scratch (__device__ globals; no allocation) ----------------
__device__ float g_T[8192 * 128];          // X_in @ theta
__device__ float g_U[8192 * 128];          // xi @ w_trans0
__device__ float g_U1[8192 * 128];         // xi @ w_trans1
__device__ float g_X[8192 * 128];          // X1 then X2
__device__ float g_msg[4096 * 128];        // edge messages (ew-scaled)
__device__ float g_msgP[8 * 4096 * 128];   // split-K partials for Hs GEMM
__device__ float g_ZP[4 * 8192 * 128];     // split-K partials for Ht^T GEMM

// ------------------------------- helpers ------------------------------------
__device__ __forceinline__ unsigned f2tf32(float f) {
    unsigned u;
    asm("cvt.rna.tf32.f32 %0, %1;" : "=r"(u) : "f"(f));
    return u;
}
// split f into tf32 hi + tf32 lo (3xTF32 scheme)
__device__ __forceinline__ void split1(float f, unsigned& hi, unsigned& lo) {
    hi = f2tf32(f);
    lo = f2tf32(f - __uint_as_float(hi));
}
__device__ __forceinline__ void split4(float4 f, uint4& hi, uint4& lo) {
    split1(f.x, hi.x, lo.x);
    split1(f.y, hi.y, lo.y);
    split1(f.z, hi.z, lo.z);
    split1(f.w, hi.w, lo.w);
}
// NOTE: non-volatile — lets ptxas interleave/pipeline HMMA with LDS/STS.
__device__ __forceinline__ void mma8(float c[4], const unsigned a[4], const unsigned b[2]) {
    asm("mma.sync.aligned.m16n8k8.row.col.f32.tf32.tf32.f32 "
        "{%0,%1,%2,%3},{%4,%5,%6,%7},{%8,%9},{%0,%1,%2,%3};"
        : "+f"(c[0]), "+f"(c[1]), "+f"(c[2]), "+f"(c[3])
        : "r"(a[0]), "r"(a[1]), "r"(a[2]), "r"(a[3]), "r"(b[0]), "r"(b[1]));
}
__device__ __forceinline__ unsigned rotl32(unsigned v, int s) {
    return __funnelshift_l(v, v, s);
}

// JAX threefry2x32, key = (0, 42). Random bits for flat element j of (8192,128).
__device__ __forceinline__ unsigned jax_dropout_bits(unsigned j) {
    const unsigned k0 = 0u, k1 = 42u;
    const unsigned ks2 = k0 ^ k1 ^ 0x1BD11BDAu;
    unsigned x0, x1;
#if JAX_PARTITIONABLE
    x0 = 0u + k0;               // hi32 of 64-bit iota
    x1 = j + k1;                // lo32
#else
    const unsigned HALF = 524288u;
    unsigned i = (j < HALF) ? j : (j - HALF);
    x0 = i + k0;
    x1 = (i + HALF) + k1;
#endif
#define TFR(r) do { x0 += x1; x1 = rotl32(x1, (r)); x1 ^= x0; } while (0)
    TFR(13); TFR(15); TFR(26); TFR(6);   x0 += k1;  x1 += ks2 + 1u;
    TFR(17); TFR(29); TFR(16); TFR(24);  x0 += ks2; x1 += k0 + 2u;
    TFR(13); TFR(15); TFR(26); TFR(6);   x0 += k0;  x1 += k1 + 3u;
    TFR(17); TFR(29); TFR(16); TFR(24);  x0 += k1;  x1 += ks2 + 4u;
    TFR(13); TFR(15); TFR(26); TFR(6);   x0 += ks2; x1 += k0 + 5u;
#undef TFR
#if JAX_PARTITIONABLE
    return x0 ^ x1;
#else
    return (j < 524288u) ? x0 : x1;
#endif
}

// ---------------------------- 3xTF32 GEMM body -------------------------------
// C[M,128] = op(A) @ B;  B is [K,128] row-major fp32.
//   TRANS_A=false: A is [M,K] row-major (row stride lda)
//   TRANS_A=true : A is [K,M] row-major (row stride lda), used as A^T
// Split `split` covers k in [split*k_iters*16, ...), writes a partial [gx*128,128]
// image at Cp + split*gx*128*128. 256 threads = 8 warps (4Mx2N), warp 32x64.
// 3xTF32: hi*hi + lo*hi + hi*lo. Double-buffered dynamic smem, 1 sync/iter.

__device__ __forceinline__ void stage_tiles(
    unsigned* __restrict__ AsH, unsigned* __restrict__ AsL,
    unsigned* __restrict__ BsH, unsigned* __restrict__ BsL,
    float4 fa0, float4 fa1, float4 fb0, float4 fb1,
    unsigned sA0, unsigned sA1, unsigned sB0, unsigned sB1)
{
    uint4 h, l;
    split4(fa0, h, l); *(uint4*)&AsH[sA0] = h; *(uint4*)&AsL[sA0] = l;
    split4(fa1, h, l); *(uint4*)&AsH[sA1] = h; *(uint4*)&AsL[sA1] = l;
    split4(fb0, h, l); *(uint4*)&BsH[sB0] = h; *(uint4*)&BsL[sB0] = l;
    split4(fb1, h, l); *(uint4*)&BsH[sB1] = h; *(uint4*)&BsL[sB1] = l;
}

template <bool TRANS_A>
__device__ __forceinline__ void gemm_body(
    const float* __restrict__ A, const float* __restrict__ B,
    float* __restrict__ Cp, int lda, int k_iters, int mblk, int split, int gx)
{
    extern __shared__ unsigned dynsm[];
    const int ASZ = TRANS_A ? (16 * 136) : (128 * 20);
    const int BSZ = 16 * 136;
    const int STRIDE = 2 * ASZ + 2 * BSZ;

    const int m0 = mblk * 128;
    const int kbase = split * k_iters * 16;
    const int tid = threadIdx.x;
    const int lane = tid & 31;
    const int wid = tid >> 5;
    const int wm = (wid & 3) * 32;
    const int wn = (wid >> 2) * 64;
    const int g = lane >> 2;   // 0..7
    const int t = lane & 3;    // 0..3

    const float *aP0, *aP1;
    unsigned sA0, sA1;
    if (TRANS_A) {
        int r0 = tid >> 5, c = (tid & 31) * 4;       // k-rows, m-cols
        aP0 = A + (size_t)(kbase + r0) * lda + m0 + c;
        aP1 = A + (size_t)(kbase + r0 + 8) * lda + m0 + c;
        sA0 = r0 * 136 + c;  sA1 = (r0 + 8) * 136 + c;
    } else {
        int r0 = tid >> 2, c = (tid & 3) * 4;        // m-rows, k-cols
        aP0 = A + (size_t)(m0 + r0) * lda + kbase + c;
        aP1 = A + (size_t)(m0 + r0 + 64) * lda + kbase + c;
        sA0 = r0 * 20 + c;   sA1 = (r0 + 64) * 20 + c;
    }
    const int br = tid >> 5, bc = (tid & 31) * 4;
    const float* bP0 = B + (size_t)(kbase + br) * 128 + bc;
    const float* bP1 = B + (size_t)(kbase + br + 8) * 128 + bc;
    const unsigned sB0 = br * 136 + bc;
    const unsigned sB1 = (br + 8) * 136 + bc;

    float acc[2][8][4];
#pragma unroll
    for (int mt = 0; mt < 2; ++mt)
#pragma unroll
        for (int nt = 0; nt < 8; ++nt)
#pragma unroll
            for (int i = 0; i < 4; ++i) acc[mt][nt][i] = 0.f;

    // prefetch tile 0 and stage into buffer 0
    float4 fa0 = *(const float4*)aP0;
    float4 fa1 = *(const float4*)aP1;
    float4 fb0 = *(const float4*)bP0;
    float4 fb1 = *(const float4*)bP1;
    stage_tiles(dynsm, dynsm + ASZ, dynsm + 2 * ASZ, dynsm + 2 * ASZ + BSZ,
                fa0, fa1, fb0, fb1, sA0, sA1, sB0, sB1);
    __syncthreads();

    const size_t aStep = TRANS_A ? (size_t)16 * lda : (size_t)16;

    for (int it = 0; it < k_iters; ++it) {
        unsigned* cur = dynsm + (it & 1) * STRIDE;
        const unsigned* cAH = cur;
        const unsigned* cAL = cur + ASZ;
        const unsigned* cBH = cur + 2 * ASZ;
        const unsigned* cBL = cur + 2 * ASZ + BSZ;
        const bool hn = (it + 1 < k_iters);

        if (hn) {  // issue next-tile global loads early (latency hidden by mmas)
            aP0 += aStep; aP1 += aStep; bP0 += 2048; bP1 += 2048;
            fa0 = *(const float4*)aP0;
            fa1 = *(const float4*)aP1;
            fb0 = *(const float4*)bP0;
            fb1 = *(const float4*)bP1;
        }

#pragma unroll
        for (int ks = 0; ks < 2; ++ks) {
            const int kk = ks * 8;
            unsigned aH[2][4], aL[2][4];
#pragma unroll
            for (int mt = 0; mt < 2; ++mt) {
                const int mb = wm + mt * 16;
                if (TRANS_A) {
                    const int i0 = (kk + t) * 136 + mb + g;
                    const int i1 = (kk + t + 4) * 136 + mb + g;
                    aH[mt][0] = cAH[i0];     aL[mt][0] = cAL[i0];
                    aH[mt][1] = cAH[i0 + 8]; aL[mt][1] = cAL[i0 + 8];
                    aH[mt][2] = cAH[i1];     aL[mt][2] = cAL[i1];
                    aH[mt][3] = cAH[i1 + 8]; aL[mt][3] = cAL[i1 + 8];
                } else {
                    const int i0 = (mb + g) * 20 + kk + t;
                    const int i1 = (mb + g + 8) * 20 + kk + t;
                    aH[mt][0] = cAH[i0];     aL[mt][0] = cAL[i0];
                    aH[mt][1] = cAH[i1];     aL[mt][1] = cAL[i1];
                    aH[mt][2] = cAH[i0 + 4]; aL[mt][2] = cAL[i0 + 4];
                    aH[mt][3] = cAH[i1 + 4]; aL[mt][3] = cAL[i1 + 4];
                }
            }
#pragma unroll
            for (int nt = 0; nt < 8; ++nt) {
                const int nb = wn + nt * 8;
                const int j0 = (kk + t) * 136 + nb + g;
                const int j1 = (kk + t + 4) * 136 + nb + g;
                unsigned bH[2] = { cBH[j0], cBH[j1] };
                unsigned bL[2] = { cBL[j0], cBL[j1] };
#pragma unroll
                for (int mt = 0; mt < 2; ++mt) {
                    mma8(acc[mt][nt], aH[mt], bH);   // hi*hi
                    mma8(acc[mt][nt], aL[mt], bH);   // lo*hi
                    mma8(acc[mt][nt], aH[mt], bL);   // hi*lo
                }
            }
        }

        if (hn) {  // stage next tile into the other buffer (overlaps with mmas)
            unsigned* nxt = dynsm + ((it + 1) & 1) * STRIDE;
            stage_tiles(nxt, nxt + ASZ, nxt + 2 * ASZ, nxt + 2 * ASZ + BSZ,
                        fa0, fa1, fb0, fb1, sA0, sA1, sB0, sB1);
        }
        __syncthreads();
    }

    float* Cb = Cp + (size_t)split * gx * (128 * 128) + (size_t)m0 * 128;
#pragma unroll
    for (int mt = 0; mt < 2; ++mt)
#pragma unroll
        for (int nt = 0; nt < 8; ++nt) {
            const int r = wm + mt * 16 + g;
            const int c = wn + nt * 8 + t * 2;
            *(float2*)&Cb[(size_t)r * 128 + c] = make_float2(acc[mt][nt][0], acc[mt][nt][1]);
            *(float2*)&Cb[(size_t)(r + 8) * 128 + c] = make_float2(acc[mt][nt][2], acc[mt][nt][3]);
        }
}

// ------------------------------ GEMM kernels ---------------------------------
template <bool TRANS_A>
__global__ __launch_bounds__(256, 2)
void gemm_big(const float* __restrict__ A, const float* __restrict__ B,
              float* __restrict__ Cp, int lda, int k_iters)
{
    gemm_body<TRANS_A>(A, B, Cp, lda, k_iters, blockIdx.x, blockIdx.y, gridDim.x);
}

struct GemmJob { const float* A; const float* B; float* C; };

__global__ __launch_bounds__(256, 2)
void gemm_small3(GemmJob j0, GemmJob j1, GemmJob j2)
{
    GemmJob j = (blockIdx.z == 0) ? j0 : ((blockIdx.z == 1) ? j1 : j2);
    gemm_body<false>(j.A, j.B, j.C, 128, 8, blockIdx.x, 0, 64);
}

// ------------------------ reduce / epilogue kernels --------------------------
__global__ void reduce_msg_k(const float* __restrict__ P, const float* __restrict__ ew,
                             float* __restrict__ out)
{
    const int i = blockIdx.x * 256 + threadIdx.x;   // 4096*128 elems
    float s = 0.f;
#pragma unroll
    for (int j = 0; j < 8; ++j) s += P[(size_t)j * (4096 * 128) + i];
    out[i] = s * ew[i >> 7];
}

__global__ void reduce_x1_k(const float* __restrict__ P, const float* __restrict__ U,
                            const float* __restrict__ bias, float* __restrict__ X1)
{
    const int i = blockIdx.x * 256 + threadIdx.x;   // 8192*128 elems
    float s = U[i] + bias[i & 127];
#pragma unroll
    for (int j = 0; j < 4; ++j) s += P[(size_t)j * (8192 * 128) + i];
    s = (s >= 0.f) ? s : 0.01f * s;                      // leaky_relu
    const unsigned bits = jax_dropout_bits((unsigned)i);
    X1[i] = (bits & 0x80000000u) ? 0.f : (s + s);        // dropout p=0.5 -> x2 scale
}

__global__ void reduce_x2_k(const float* __restrict__ P, const float* __restrict__ U,
                            const float* __restrict__ bias, float* __restrict__ X2)
{
    const int i = blockIdx.x * 256 + threadIdx.x;
    float s = U[i] + bias[i & 127];
#pragma unroll
    for (int j = 0; j < 4; ++j) s += P[(size_t)j * (8192 * 128) + i];
    s = (s >= 0.f) ? s : 0.01f * s;                      // conv lrelu
    s = (s >= 0.f) ? s : 0.01f * s;                      // forward lrelu
    X2[i] = s;
}

__global__ void fc_k(const float* __restrict__ X, const float* __restrict__ state,
                     const float* __restrict__ fcw, const float* __restrict__ fcb,
                     float* __restrict__ out)
{
    const int n = blockIdx.x * 256 + threadIdx.x;   // 8192 rows
    const float4* xr = (const float4*)(X + (size_t)n * 128);
    const float4* w4 = (const float4*)fcw;
    float s = 0.f;
#pragma unroll
    for (int i = 0; i < 32; ++i) {
        float4 a = xr[i], b = w4[i];
        s += a.x * b.x + a.y * b.y + a.z * b.z + a.w * b.w;
    }
    out[n] = s + state[n] * fcw[128] + fcb[0];
}

// --------------------------------- launch ------------------------------------
extern "C" void kernel_launch(void* const* d_in, const int* in_sizes, int n_in,
                              void* d_out, int out_size)
{
    const float* xi   = (const float*)d_in[0];
    const float* x    = (const float*)d_in[1];
    const float* Ht   = (const float*)d_in[2];
    const float* Hs   = (const float*)d_in[3];
    const float* st   = (const float*)d_in[4];
    const float* w0   = (const float*)d_in[5];
    const float* th0  = (const float*)d_in[6];
    const float* ew0  = (const float*)d_in[7];
    const float* b0   = (const float*)d_in[8];
    const float* w1   = (const float*)d_in[9];
    const float* th1  = (const float*)d_in[10];
    const float* ew1  = (const float*)d_in[11];
    const float* b1   = (const float*)d_in[12];
    const float* fcw  = (const float*)d_in[13];
    const float* fcb  = (const float*)d_in[14];
    float* out = (float*)d_out;

    float *T, *U, *U1, *X, *M, *MP, *ZP;
    cudaGetSymbolAddress((void**)&T,  g_T);
    cudaGetSymbolAddress((void**)&U,  g_U);
    cudaGetSymbolAddress((void**)&U1, g_U1);
    cudaGetSymbolAddress((void**)&X,  g_X);
    cudaGetSymbolAddress((void**)&M,  g_msg);
    cudaGetSymbolAddress((void**)&MP, g_msgP);
    cudaGetSymbolAddress((void**)&ZP, g_ZP);

    // dynamic smem: 2 buffers x (2*ASZ + 2*BSZ) unsigneds
    const int SM_NT = (2 * (128 * 20) + 2 * (16 * 136)) * 2 * 4;   // 75776 B
    const int SM_T  = (2 * (16 * 136) + 2 * (16 * 136)) * 2 * 4;   // 69632 B
    cudaFuncSetAttribute(gemm_big<false>, cudaFuncAttributeMaxDynamicSharedMemorySize, SM_NT);
    cudaFuncSetAttribute(gemm_big<true>,  cudaFuncAttributeMaxDynamicSharedMemorySize, SM_T);
    cudaFuncSetAttribute(gemm_small3,     cudaFuncAttributeMaxDynamicSharedMemorySize, SM_NT);

    // ---- independent small GEMMs batched: T0 = x@th0, U = xi@w0, U1 = xi@w1 ----
    GemmJob j0 = { x,  th0, T  };
    GemmJob j1 = { xi, w0,  U  };
    GemmJob j2 = { xi, w1,  U1 };
    gemm_small3<<<dim3(64, 1, 3), 256, SM_NT>>>(j0, j1, j2);

    // ---- layer 0 ----
    gemm_big<false><<<dim3(32, 8), 256, SM_NT>>>(Hs, T, MP, 8192, 64);  // msg partials
    reduce_msg_k<<<2048, 256>>>(MP, ew0, M);
    gemm_big<true ><<<dim3(64, 4), 256, SM_T >>>(Ht, M, ZP, 8192, 64);  // Z partials
    reduce_x1_k<<<4096, 256>>>(ZP, U, b0, X);                           // X1

    // ---- layer 1 ----
    gemm_big<false><<<dim3(64, 1), 256, SM_NT>>>(X,  th1, T,  128,  8); // T1 = X1@th1
    gemm_big<false><<<dim3(32, 8), 256, SM_NT>>>(Hs, T,   MP, 8192, 64);
    reduce_msg_k<<<2048, 256>>>(MP, ew1, M);
    gemm_big<true ><<<dim3(64, 4), 256, SM_T >>>(Ht, M,   ZP, 8192, 64);
    reduce_x2_k<<<4096, 256>>>(ZP, U1, b1, X);                          // X2 (double lrelu)

    // ---- head ----
    fc_k<<<32, 256>>>(X, st, fcw, fcb, out);
}

// round 9
// speedup vs baseline: 1.6593x; 1.6190x over previous
#include <cuda_runtime.h>
#include <cuda_bf16.h>

#define JAX_PARTITIONABLE 1

// ---------------- scratch (__device__ globals; no allocation) ----------------
__device__ float g_T[8192 * 128];          // X_in @ theta
__device__ float g_U[8192 * 128];          // xi @ w_trans0
__device__ float g_U1[8192 * 128];         // xi @ w_trans1
__device__ float g_X[8192 * 128];          // X1 then X2
__device__ float g_msg[4096 * 128];        // edge messages (ew-scaled)
__device__ float g_msgP[8 * 4096 * 128];   // split-K partials for Hs GEMM
__device__ float g_ZP[4 * 8192 * 128];     // split-K partials for Ht^T GEMM

// ------------------------------- helpers ------------------------------------
__device__ __forceinline__ unsigned rotl32(unsigned v, int s) {
    return __funnelshift_l(v, v, s);
}

// bf16 2-way split of a k-pair (f0 = even k, f1 = odd k) -> packed hi, lo u32.
// hi captures top ~8 mantissa bits; lo the next ~9. Combined ~2^-18 residual.
__device__ __forceinline__ void split_pair(float f0, float f1,
                                           unsigned& H, unsigned& L) {
    __nv_bfloat162 h = __floats2bfloat162_rn(f0, f1);   // .x = f0 (low 16 bits)
    float r0 = f0 - __bfloat162float(h.x);
    float r1 = f1 - __bfloat162float(h.y);
    __nv_bfloat162 l = __floats2bfloat162_rn(r0, r1);
    H = *reinterpret_cast<unsigned*>(&h);
    L = *reinterpret_cast<unsigned*>(&l);
}

// m16n8k16 bf16 mma, fp32 accumulate
__device__ __forceinline__ void mma16(float c[4], const unsigned a[4], const unsigned b[2]) {
    asm("mma.sync.aligned.m16n8k16.row.col.f32.bf16.bf16.f32 "
        "{%0,%1,%2,%3},{%4,%5,%6,%7},{%8,%9},{%0,%1,%2,%3};"
        : "+f"(c[0]), "+f"(c[1]), "+f"(c[2]), "+f"(c[3])
        : "r"(a[0]), "r"(a[1]), "r"(a[2]), "r"(a[3]), "r"(b[0]), "r"(b[1]));
}

// JAX threefry2x32, key = (0, 42). Random bits for flat element j of (8192,128).
__device__ __forceinline__ unsigned jax_dropout_bits(unsigned j) {
    const unsigned k0 = 0u, k1 = 42u;
    const unsigned ks2 = k0 ^ k1 ^ 0x1BD11BDAu;
    unsigned x0, x1;
#if JAX_PARTITIONABLE
    x0 = 0u + k0;
    x1 = j + k1;
#else
    const unsigned HALF = 524288u;
    unsigned i = (j < HALF) ? j : (j - HALF);
    x0 = i + k0;
    x1 = (i + HALF) + k1;
#endif
#define TFR(r) do { x0 += x1; x1 = rotl32(x1, (r)); x1 ^= x0; } while (0)
    TFR(13); TFR(15); TFR(26); TFR(6);   x0 += k1;  x1 += ks2 + 1u;
    TFR(17); TFR(29); TFR(16); TFR(24);  x0 += ks2; x1 += k0 + 2u;
    TFR(13); TFR(15); TFR(26); TFR(6);   x0 += k0;  x1 += k1 + 3u;
    TFR(17); TFR(29); TFR(16); TFR(24);  x0 += k1;  x1 += ks2 + 4u;
    TFR(13); TFR(15); TFR(26); TFR(6);   x0 += ks2; x1 += k0 + 5u;
#undef TFR
#if JAX_PARTITIONABLE
    return x0 ^ x1;
#else
    return (j < 524288u) ? x0 : x1;
#endif
}

// ====================== 3-term bf16-split GEMM ===============================
// C[M,128] = op(A) @ B;  B is [K,128] row-major fp32.
//   TRANS_A=false: A [M,K] row-major (row stride lda)
//   TRANS_A=true : A [K,M] row-major (row stride lda), used as A^T
// 512 threads = 16 warps (4M x 4N), warp tile 32x32, k32 per iteration,
// double-buffered smem, register prefetch of the next tile, 1 sync/iter.
// SMEM layout per buffer (u32):
//   AsH[128 rows][20]  (16 k-pairs + 4 pad)   2560
//   AsL  same                                  2560
//   BsH[16 k-pairs][136] (128 n + 8 pad)       2176
//   BsL  same                                  2176
static const int ASZ = 2560, BSZ = 2176;
static const int BUF_STRIDE = 2 * ASZ + 2 * BSZ;   // 9472 u32
static const int SM_BYTES = BUF_STRIDE * 2 * 4;    // 75776 B

template <bool TRANS_A>
__device__ __forceinline__ float4 loadA(const float* __restrict__ A, int lda,
                                        int m0, int kc, int row, int kq) {
    if (TRANS_A) {
        const float* p = A + (size_t)(kc + kq * 4) * lda + m0 + row;
        float4 v;
        v.x = p[0];
        v.y = p[(size_t)lda];
        v.z = p[2 * (size_t)lda];
        v.w = p[3 * (size_t)lda];
        return v;
    } else {
        return *(const float4*)(A + (size_t)(m0 + row) * lda + kc + kq * 4);
    }
}

__device__ __forceinline__ void stA(unsigned* __restrict__ AsH,
                                    unsigned* __restrict__ AsL,
                                    int row, int kq, float4 v) {
    unsigned h0, l0, h1, l1;
    split_pair(v.x, v.y, h0, l0);
    split_pair(v.z, v.w, h1, l1);
    *(uint2*)&AsH[row * 20 + 2 * kq] = make_uint2(h0, h1);
    *(uint2*)&AsL[row * 20 + 2 * kq] = make_uint2(l0, l1);
}

__device__ __forceinline__ void stB(unsigned* __restrict__ BsH,
                                    unsigned* __restrict__ BsL,
                                    int p, int n, float4 r0, float4 r1) {
    unsigned h[4], l[4];
    split_pair(r0.x, r1.x, h[0], l[0]);
    split_pair(r0.y, r1.y, h[1], l[1]);
    split_pair(r0.z, r1.z, h[2], l[2]);
    split_pair(r0.w, r1.w, h[3], l[3]);
    *(uint4*)&BsH[p * 136 + n] = make_uint4(h[0], h[1], h[2], h[3]);
    *(uint4*)&BsL[p * 136 + n] = make_uint4(l[0], l[1], l[2], l[3]);
}

template <bool TRANS_A>
__device__ __forceinline__ void gemm_body_bf(
    const float* __restrict__ A, const float* __restrict__ B,
    float* __restrict__ Cp, int lda, int k_iters, int mblk, int split, int gx)
{
    extern __shared__ unsigned sm[];
    const int tid = threadIdx.x;
    const int lane = tid & 31;
    const int wid = tid >> 5;              // 0..15
    const int wm = (wid & 3) * 32;
    const int wn = (wid >> 2) * 32;
    const int g = lane >> 2;               // 0..7
    const int t = lane & 3;                // 0..3
    const int m0 = mblk * 128;
    const int k00 = split * k_iters * 32;

    // staging geometry (per thread): A -> 2 rounds of one float4; B -> 2 float4
    int ar_row[2], ar_kq[2];
#pragma unroll
    for (int r = 0; r < 2; ++r) {
        int task = tid + r * 512;
        if (TRANS_A) { ar_row[r] = task & 127; ar_kq[r] = task >> 7; }
        else         { ar_row[r] = task >> 3;  ar_kq[r] = task & 7;  }
    }
    const int b_p = tid >> 5;              // 0..15 (k-pair)
    const int b_n = (tid & 31) * 4;        // n quad

    float acc[2][4][4];
#pragma unroll
    for (int mt = 0; mt < 2; ++mt)
#pragma unroll
        for (int nt = 0; nt < 4; ++nt)
#pragma unroll
            for (int i = 0; i < 4; ++i) acc[mt][nt][i] = 0.f;

    // prologue: load + stage tile 0 into buffer 0
    int kc = k00;
    float4 av0 = loadA<TRANS_A>(A, lda, m0, kc, ar_row[0], ar_kq[0]);
    float4 av1 = loadA<TRANS_A>(A, lda, m0, kc, ar_row[1], ar_kq[1]);
    float4 bv0 = *(const float4*)(B + (size_t)(kc + 2 * b_p) * 128 + b_n);
    float4 bv1 = *(const float4*)(B + (size_t)(kc + 2 * b_p + 1) * 128 + b_n);
    stA(sm, sm + ASZ, ar_row[0], ar_kq[0], av0);
    stA(sm, sm + ASZ, ar_row[1], ar_kq[1], av1);
    stB(sm + 2 * ASZ, sm + 2 * ASZ + BSZ, b_p, b_n, bv0, bv1);
    __syncthreads();

    for (int it = 0; it < k_iters; ++it) {
        const unsigned* cur = sm + (it & 1) * BUF_STRIDE;
        const unsigned* cAH = cur;
        const unsigned* cAL = cur + ASZ;
        const unsigned* cBH = cur + 2 * ASZ;
        const unsigned* cBL = cur + 2 * ASZ + BSZ;
        const bool hn = (it + 1 < k_iters);

        if (hn) {  // issue next-tile global loads early (hidden under mmas)
            kc = k00 + (it + 1) * 32;
            av0 = loadA<TRANS_A>(A, lda, m0, kc, ar_row[0], ar_kq[0]);
            av1 = loadA<TRANS_A>(A, lda, m0, kc, ar_row[1], ar_kq[1]);
            bv0 = *(const float4*)(B + (size_t)(kc + 2 * b_p) * 128 + b_n);
            bv1 = *(const float4*)(B + (size_t)(kc + 2 * b_p + 1) * 128 + b_n);
        }

#pragma unroll
        for (int ks = 0; ks < 2; ++ks) {          // two k16 sub-steps
            const int pb = ks * 8;                // pair base
            unsigned aH[2][4], aL[2][4];
#pragma unroll
            for (int mt = 0; mt < 2; ++mt) {
                const int r0 = (wm + mt * 16 + g) * 20;
                const int r1 = r0 + 8 * 20;
                aH[mt][0] = cAH[r0 + pb + t];
                aH[mt][1] = cAH[r1 + pb + t];
                aH[mt][2] = cAH[r0 + pb + t + 4];
                aH[mt][3] = cAH[r1 + pb + t + 4];
                aL[mt][0] = cAL[r0 + pb + t];
                aL[mt][1] = cAL[r1 + pb + t];
                aL[mt][2] = cAL[r0 + pb + t + 4];
                aL[mt][3] = cAL[r1 + pb + t + 4];
            }
#pragma unroll
            for (int nt = 0; nt < 4; ++nt) {
                const int nb = wn + nt * 8 + g;
                const int j0 = (pb + t) * 136 + nb;
                const int j1 = (pb + t + 4) * 136 + nb;
                unsigned bH[2] = { cBH[j0], cBH[j1] };
                unsigned bL[2] = { cBL[j0], cBL[j1] };
#pragma unroll
                for (int mt = 0; mt < 2; ++mt) {
                    mma16(acc[mt][nt], aH[mt], bH);   // hi*hi
                    mma16(acc[mt][nt], aL[mt], bH);   // lo*hi
                    mma16(acc[mt][nt], aH[mt], bL);   // hi*lo
                }
            }
        }

        if (hn) {  // stage next tile into the other buffer
            unsigned* nxt = sm + ((it + 1) & 1) * BUF_STRIDE;
            stA(nxt, nxt + ASZ, ar_row[0], ar_kq[0], av0);
            stA(nxt, nxt + ASZ, ar_row[1], ar_kq[1], av1);
            stB(nxt + 2 * ASZ, nxt + 2 * ASZ + BSZ, b_p, b_n, bv0, bv1);
        }
        __syncthreads();
    }

    float* Cb = Cp + (size_t)split * gx * (128 * 128) + (size_t)m0 * 128;
#pragma unroll
    for (int mt = 0; mt < 2; ++mt)
#pragma unroll
        for (int nt = 0; nt < 4; ++nt) {
            const int r = wm + mt * 16 + g;
            const int c = wn + nt * 8 + t * 2;
            *(float2*)&Cb[(size_t)r * 128 + c] =
                make_float2(acc[mt][nt][0], acc[mt][nt][1]);
            *(float2*)&Cb[(size_t)(r + 8) * 128 + c] =
                make_float2(acc[mt][nt][2], acc[mt][nt][3]);
        }
}

// ------------------------------ GEMM kernels ---------------------------------
template <bool TRANS_A>
__global__ __launch_bounds__(512, 1)
void gemm_big(const float* __restrict__ A, const float* __restrict__ B,
              float* __restrict__ Cp, int lda, int k_iters)
{
    gemm_body_bf<TRANS_A>(A, B, Cp, lda, k_iters, blockIdx.x, blockIdx.y, gridDim.x);
}

struct GemmJob { const float* A; const float* B; float* C; };

__global__ __launch_bounds__(512, 1)
void gemm_small3(GemmJob j0, GemmJob j1, GemmJob j2)
{
    GemmJob j = (blockIdx.z == 0) ? j0 : ((blockIdx.z == 1) ? j1 : j2);
    gemm_body_bf<false>(j.A, j.B, j.C, 128, 4, blockIdx.x, 0, 64);
}

__global__ __launch_bounds__(512, 1)
void gemm_small1(const float* __restrict__ A, const float* __restrict__ B,
                 float* __restrict__ C)
{
    gemm_body_bf<false>(A, B, C, 128, 4, blockIdx.x, 0, 64);
}

// ------------------------ reduce / epilogue kernels --------------------------
__global__ void reduce_msg_k(const float* __restrict__ P, const float* __restrict__ ew,
                             float* __restrict__ out)
{
    const int i = blockIdx.x * 256 + threadIdx.x;
    float s = 0.f;
#pragma unroll
    for (int j = 0; j < 8; ++j) s += P[(size_t)j * (4096 * 128) + i];
    out[i] = s * ew[i >> 7];
}

__global__ void reduce_x1_k(const float* __restrict__ P, const float* __restrict__ U,
                            const float* __restrict__ bias, float* __restrict__ X1)
{
    const int i = blockIdx.x * 256 + threadIdx.x;
    float s = U[i] + bias[i & 127];
#pragma unroll
    for (int j = 0; j < 4; ++j) s += P[(size_t)j * (8192 * 128) + i];
    s = (s >= 0.f) ? s : 0.01f * s;
    const unsigned bits = jax_dropout_bits((unsigned)i);
    X1[i] = (bits & 0x80000000u) ? 0.f : (s + s);
}

__global__ void reduce_x2_k(const float* __restrict__ P, const float* __restrict__ U,
                            const float* __restrict__ bias, float* __restrict__ X2)
{
    const int i = blockIdx.x * 256 + threadIdx.x;
    float s = U[i] + bias[i & 127];
#pragma unroll
    for (int j = 0; j < 4; ++j) s += P[(size_t)j * (8192 * 128) + i];
    s = (s >= 0.f) ? s : 0.01f * s;
    s = (s >= 0.f) ? s : 0.01f * s;
    X2[i] = s;
}

__global__ void fc_k(const float* __restrict__ X, const float* __restrict__ state,
                     const float* __restrict__ fcw, const float* __restrict__ fcb,
                     float* __restrict__ out)
{
    const int n = blockIdx.x * 256 + threadIdx.x;
    const float4* xr = (const float4*)(X + (size_t)n * 128);
    const float4* w4 = (const float4*)fcw;
    float s = 0.f;
#pragma unroll
    for (int i = 0; i < 32; ++i) {
        float4 a = xr[i], b = w4[i];
        s += a.x * b.x + a.y * b.y + a.z * b.z + a.w * b.w;
    }
    out[n] = s + state[n] * fcw[128] + fcb[0];
}

// --------------------------------- launch ------------------------------------
extern "C" void kernel_launch(void* const* d_in, const int* in_sizes, int n_in,
                              void* d_out, int out_size)
{
    const float* xi   = (const float*)d_in[0];
    const float* x    = (const float*)d_in[1];
    const float* Ht   = (const float*)d_in[2];
    const float* Hs   = (const float*)d_in[3];
    const float* st   = (const float*)d_in[4];
    const float* w0   = (const float*)d_in[5];
    const float* th0  = (const float*)d_in[6];
    const float* ew0  = (const float*)d_in[7];
    const float* b0   = (const float*)d_in[8];
    const float* w1   = (const float*)d_in[9];
    const float* th1  = (const float*)d_in[10];
    const float* ew1  = (const float*)d_in[11];
    const float* b1   = (const float*)d_in[12];
    const float* fcw  = (const float*)d_in[13];
    const float* fcb  = (const float*)d_in[14];
    float* out = (float*)d_out;

    float *T, *U, *U1, *X, *M, *MP, *ZP;
    cudaGetSymbolAddress((void**)&T,  g_T);
    cudaGetSymbolAddress((void**)&U,  g_U);
    cudaGetSymbolAddress((void**)&U1, g_U1);
    cudaGetSymbolAddress((void**)&X,  g_X);
    cudaGetSymbolAddress((void**)&M,  g_msg);
    cudaGetSymbolAddress((void**)&MP, g_msgP);
    cudaGetSymbolAddress((void**)&ZP, g_ZP);

    cudaFuncSetAttribute(gemm_big<false>, cudaFuncAttributeMaxDynamicSharedMemorySize, SM_BYTES);
    cudaFuncSetAttribute(gemm_big<true>,  cudaFuncAttributeMaxDynamicSharedMemorySize, SM_BYTES);
    cudaFuncSetAttribute(gemm_small3,     cudaFuncAttributeMaxDynamicSharedMemorySize, SM_BYTES);
    cudaFuncSetAttribute(gemm_small1,     cudaFuncAttributeMaxDynamicSharedMemorySize, SM_BYTES);

    // independent small GEMMs: T = x@th0, U = xi@w0, U1 = xi@w1
    GemmJob j0 = { x,  th0, T  };
    GemmJob j1 = { xi, w0,  U  };
    GemmJob j2 = { xi, w1,  U1 };
    gemm_small3<<<dim3(64, 1, 3), 512, SM_BYTES>>>(j0, j1, j2);

    // ---- layer 0 ----
    gemm_big<false><<<dim3(32, 8), 512, SM_BYTES>>>(Hs, T, MP, 8192, 32);
    reduce_msg_k<<<2048, 256>>>(MP, ew0, M);
    gemm_big<true ><<<dim3(64, 4), 512, SM_BYTES>>>(Ht, M, ZP, 8192, 32);
    reduce_x1_k<<<4096, 256>>>(ZP, U, b0, X);

    // ---- layer 1 ----
    gemm_small1<<<64, 512, SM_BYTES>>>(X, th1, T);
    gemm_big<false><<<dim3(32, 8), 512, SM_BYTES>>>(Hs, T, MP, 8192, 32);
    reduce_msg_k<<<2048, 256>>>(MP, ew1, M);
    gemm_big<true ><<<dim3(64, 4), 512, SM_BYTES>>>(Ht, M, ZP, 8192, 32);
    reduce_x2_k<<<4096, 256>>>(ZP, U1, b1, X);

    // ---- head ----
    fc_k<<<32, 256>>>(X, st, fcw, fcb, out);
}